// round 15
// baseline (speedup 1.0000x reference)
#include <cuda_runtime.h>
#include <math.h>

#define DIMD 128
#define PMAX 3136

typedef unsigned long long ull;

// Scratch: RECIPROCAL of diag(inv(b_covs[p]))[d], stored [D][P].
__device__ float g_rdinv[DIMD * PMAX];

// ---- packed f32x2 helpers (Blackwell sm_103a) ------------------------------
__device__ __forceinline__ ull pack2(float lo, float hi) {
    ull r; asm("mov.b64 %0, {%1, %2};" : "=l"(r) : "f"(lo), "f"(hi)); return r;
}
__device__ __forceinline__ float2 unpack2(ull v) {
    float2 r; asm("mov.b64 {%0, %1}, %2;" : "=f"(r.x), "=f"(r.y) : "l"(v)); return r;
}
__device__ __forceinline__ ull fma2(ull a, ull b, ull c) {
    ull d; asm("fma.rn.f32x2 %0, %1, %2, %3;" : "=l"(d) : "l"(a), "l"(b), "l"(c)); return d;
}
__device__ __forceinline__ ull mul2(ull a, ull b) {
    ull d; asm("mul.rn.f32x2 %0, %1, %2;" : "=l"(d) : "l"(a), "l"(b)); return d;
}
// Fast reciprocal: rcp.approx + 1 Newton step (fp32-accurate).
__device__ __forceinline__ float frcp(float x) {
    float r; asm("rcp.approx.ftz.f32 %0, %1;" : "=f"(r) : "f"(x));
    return r * fmaf(-x, r, 2.0f);
}

// ---------------------------------------------------------------------------
// Phase A: packed-f32x2 Gauss-Jordan with ROW-PAIR packing.
//   Tp[ap][b] = ( M[R0+2ap][C0+b] , M[R0+2ap+1][C0+b] )   ap=0..3, b=0..7
// Why: the rank-1 multiplier ci (pivot column) is then two ADJACENT floats
// of the raw colbuf => comes packed straight from LDS.128 with ZERO pack2
// MOVs (R13 profile: alu pipe 41% from exactly those MOVs). The duplicated
// operand moves to the pivot ROW, staged as (v,v) ull pairs by only the 16
// row-staging threads. Column staging is a direct STS.64 of Tp[ap][KNQ].
// Hot-path ALU per thread per step: ~2 MOVs (npv2 only).
// ---------------------------------------------------------------------------
template<int KQ>
__device__ __forceinline__ void gj_step(
    ull (&Tp)[4][8],
    float (&colbuf)[2][DIMD], ull (&pivD)[2][DIMD],
    int kk, int ty, int tx, int R0, int C0)
{
    constexpr int BUF  = KQ & 1;
    constexpr int NBUF = BUF ^ 1;
    constexpr int KNQ  = (KQ + 1) & 7;
    constexpr int AP   = KQ >> 1;      // pair index of pivot row in its block
    constexpr int HH   = KQ & 1;       // half within the pair
    const int k = (kk << 3) + KQ;

    float pv  = frcp(colbuf[BUF][k]);
    float npv = -pv;
    ull npv2  = pack2(npv, npv);

    // Pivot column: adjacent rows are adjacent floats -> packed for free.
    ull ci2[4];
    {
        const ulonglong2* c4 = reinterpret_cast<const ulonglong2*>(&colbuf[BUF][R0]);
        ulonglong2 u0 = c4[0], u1 = c4[1];
        ci2[0]=u0.x; ci2[1]=u0.y; ci2[2]=u1.x; ci2[3]=u1.y;
    }

    // Pivot row, pre-duplicated (v,v) pairs; scale by -pv on the fma pipe.
    ull sn2[8];
    {
        const ulonglong2* r4 = reinterpret_cast<const ulonglong2*>(&pivD[BUF][C0]);
        ulonglong2 u0 = r4[0], u1 = r4[1], u2 = r4[2], u3 = r4[3];
        sn2[0]=mul2(u0.x,npv2); sn2[1]=mul2(u0.y,npv2);
        sn2[2]=mul2(u1.x,npv2); sn2[3]=mul2(u1.y,npv2);
        sn2[4]=mul2(u2.x,npv2); sn2[5]=mul2(u2.y,npv2);
        sn2[6]=mul2(u3.x,npv2); sn2[7]=mul2(u3.y,npv2);
    }

    // Rank-1 update: 32 packed FMAs.  Tp += ci * (-row*pv)
#pragma unroll
    for (int ap = 0; ap < 4; ap++)
#pragma unroll
        for (int b = 0; b < 8; b++)
            Tp[ap][b] = fma2(ci2[ap], sn2[b], Tp[ap][b]);

    // Pivot-row fixup: M[k][j] = row_k[j]*pv = -sn[j]  (both sn halves equal).
    if (kk == ty) {
#pragma unroll
        for (int b = 0; b < 8; b++) {
            float2 h = unpack2(Tp[AP][b]);
            float v = -unpack2(sn2[b]).x;
            if (HH) h.y = v; else h.x = v;
            Tp[AP][b] = pack2(h.x, h.y);
        }
    }
    // Pivot-col fixup: M[i][k] = -ci[i]*pv (pairs), then M[k][k] = pv.
    if (kk == tx) {
#pragma unroll
        for (int ap = 0; ap < 4; ap++)
            Tp[ap][KQ] = mul2(ci2[ap], npv2);
        if (kk == ty) {
            float2 h = unpack2(Tp[AP][KQ]);
            if (HH) h.y = pv; else h.x = pv;
            Tp[AP][KQ] = pack2(h.x, h.y);
        }
    }

    // Stage next pivot column/row from the UPDATED matrix.
    if (k + 1 < DIMD) {
        constexpr int APN = KNQ >> 1;
        constexpr int HN  = KNQ & 1;
        const int kkn = kk + ((KQ + 1) >> 3);
        if (kkn == tx) {
            // Column KNQ: each pair is two consecutive raw floats -> STS.64.
            ull* dst = reinterpret_cast<ull*>(&colbuf[NBUF][R0]);
#pragma unroll
            for (int ap = 0; ap < 4; ap++) dst[ap] = Tp[ap][KNQ];
        }
        if (kkn == ty) {
            // Row k+1: extract half, store duplicated pairs (16 threads only).
#pragma unroll
            for (int b = 0; b < 8; b++) {
                float2 h = unpack2(Tp[APN][b]);
                float v = HN ? h.y : h.x;
                pivD[NBUF][C0 + b] = pack2(v, v);
            }
        }
    }
    __syncthreads();
}

__global__ __launch_bounds__(256, 2)
void inv_diag_kernel(const float* __restrict__ covs, int P)
{
    int p = blockIdx.x;
    const float* A = covs + (size_t)p * DIMD * DIMD;

    int tid = threadIdx.x;
    int ty = tid >> 4;
    int tx = tid & 15;
    int R0 = ty << 3;
    int C0 = tx << 3;

    // Row-pair packed tile: Tp[ap][b] = (M[R0+2ap][C0+b], M[R0+2ap+1][C0+b]).
    ull Tp[4][8];
#pragma unroll
    for (int ap = 0; ap < 4; ap++) {
        const float4* r0 = reinterpret_cast<const float4*>(A + (size_t)(R0 + 2*ap)     * DIMD + C0);
        const float4* r1 = reinterpret_cast<const float4*>(A + (size_t)(R0 + 2*ap + 1) * DIMD + C0);
        float4 a0 = r0[0], a1 = r0[1];
        float4 b0 = r1[0], b1 = r1[1];
        Tp[ap][0] = pack2(a0.x, b0.x); Tp[ap][1] = pack2(a0.y, b0.y);
        Tp[ap][2] = pack2(a0.z, b0.z); Tp[ap][3] = pack2(a0.w, b0.w);
        Tp[ap][4] = pack2(a1.x, b1.x); Tp[ap][5] = pack2(a1.y, b1.y);
        Tp[ap][6] = pack2(a1.z, b1.z); Tp[ap][7] = pack2(a1.w, b1.w);
    }

    __shared__ __align__(16) float colbuf[2][DIMD];  // raw pivot column M[:,k]
    __shared__ __align__(16) ull   pivD[2][DIMD];    // pivot row, (v,v) pairs

    // Stage step 0.
    if (tx == 0) {
        ull* dst = reinterpret_cast<ull*>(&colbuf[0][R0]);
#pragma unroll
        for (int ap = 0; ap < 4; ap++) dst[ap] = Tp[ap][0];
    }
    if (ty == 0) {
#pragma unroll
        for (int b = 0; b < 8; b++) {
            float v = unpack2(Tp[0][b]).x;   // row 0 = half x of pair 0
            pivD[0][C0 + b] = pack2(v, v);
        }
    }
    __syncthreads();

#pragma unroll 1
    for (int kk = 0; kk < 16; kk++) {
        gj_step<0>(Tp, colbuf, pivD, kk, ty, tx, R0, C0);
        gj_step<1>(Tp, colbuf, pivD, kk, ty, tx, R0, C0);
        gj_step<2>(Tp, colbuf, pivD, kk, ty, tx, R0, C0);
        gj_step<3>(Tp, colbuf, pivD, kk, ty, tx, R0, C0);
        gj_step<4>(Tp, colbuf, pivD, kk, ty, tx, R0, C0);
        gj_step<5>(Tp, colbuf, pivD, kk, ty, tx, R0, C0);
        gj_step<6>(Tp, colbuf, pivD, kk, ty, tx, R0, C0);
        gj_step<7>(Tp, colbuf, pivD, kk, ty, tx, R0, C0);
    }

    // Registers hold inv(A). Diagonal element a sits in pair a>>1, half a&1.
    if (ty == tx) {
#pragma unroll
        for (int a = 0; a < 8; a++) {
            float2 h = unpack2(Tp[a >> 1][a]);
            float dv = (a & 1) ? h.y : h.x;
            g_rdinv[(size_t)(R0 + a) * P + p] = frcp(dv);
        }
    }
}

// ncu alignment: 3 launches per kernel_launch call => the profiled launch
// (index 3 of the timed sequence) is call 2's inv_diag_kernel.
__global__ void nop_pad_kernel() {}

// ---------------------------------------------------------------------------
// Phase B: streaming whitening + cosine similarity, coalesced:
// block = 256 threads = 64 outputs x 4 d-quarters; a warp's 32 lanes read 32
// consecutive p => full 128B transactions. Cross-quarter reduction via smem.
// ---------------------------------------------------------------------------
__global__ void ace_kernel(const float* __restrict__ X,
                           const float* __restrict__ bmean,
                           const float* __restrict__ covs,
                           const float* __restrict__ sig,
                           const int* __restrict__ covtype,
                           float* __restrict__ out,
                           int B, int P)
{
    int t    = threadIdx.x;
    int sub  = t >> 6;
    int slot = t & 63;
    int idx  = blockIdx.x * 64 + slot;
    bool valid = idx < B * P;
    int b = valid ? idx / P : 0;
    int p = valid ? idx - b * P : 0;
    int ct = *covtype;

    float ww = 0.f, ws = 0.f, ss = 0.f;

    if (valid) {
        if (ct == 0) {
            for (int m = sub * 32; m < sub * 32 + 32; m++) {
                float w = 0.f;
                const float* cr = covs + ((size_t)p * DIMD + m) * DIMD;
                for (int d = 0; d < DIMD; d++) {
                    float xc = X[((size_t)b * DIMD + d) * P + p] - bmean[(size_t)d * P + p];
                    w = fmaf(xc, cr[d], w);
                }
                float s = sig[(size_t)m * P + p];
                ww = fmaf(w, w, ww);
                ws = fmaf(w, s, ws);
                ss = fmaf(s, s, ss);
            }
        } else {
            bool use_diag = (ct == 1);
            int d0 = sub * 32;
#pragma unroll 16
            for (int i = 0; i < 32; i++) {
                int d = d0 + i;
                float xc = X[((size_t)b * DIMD + d) * P + p] - bmean[(size_t)d * P + p];
                float s  = sig[(size_t)d * P + p];
                float w  = use_diag ? (xc * g_rdinv[(size_t)d * P + p]) : xc;
                ww = fmaf(w, w, ww);
                ws = fmaf(w, s, ws);
                ss = fmaf(s, s, ss);
            }
        }
    }

    __shared__ float sred[3][4][64];
    sred[0][sub][slot] = ww;
    sred[1][sub][slot] = ws;
    sred[2][sub][slot] = ss;
    __syncthreads();

    if (sub == 0 && valid) {
        float tw = 0.f, ts = 0.f, tq = 0.f;
#pragma unroll
        for (int q = 0; q < 4; q++) {
            tw += sred[0][q][slot];
            ts += sred[1][q][slot];
            tq += sred[2][q][slot];
        }
        float denom = fmaxf(sqrtf(tw), 1e-12f) * fmaxf(sqrtf(tq), 1e-12f);
        out[idx] = ts / denom;
    }
}

extern "C" void kernel_launch(void* const* d_in, const int* in_sizes, int n_in,
                              void* d_out, int out_size)
{
    const float* X      = (const float*)d_in[0];
    const float* bmean  = (const float*)d_in[1];
    const float* covs   = (const float*)d_in[2];
    const float* sig    = (const float*)d_in[3];
    const int*   ctype  = (const int*)d_in[4];
    float*       out    = (float*)d_out;

    int P = in_sizes[2] / (DIMD * DIMD);           // 3136
    int B = in_sizes[0] / (DIMD * P);              // 32

    inv_diag_kernel<<<P, 256>>>(covs, P);

    int total = B * P;
    ace_kernel<<<(total + 63) / 64, 256>>>(X, bmean, covs, sig, ctype, out, B, P);

    nop_pad_kernel<<<1, 32>>>();   // keep ncu aimed at inv_diag_kernel
}

// round 16
// speedup vs baseline: 2.2165x; 2.2165x over previous
#include <cuda_runtime.h>
#include <math.h>

#define DIMD 128
#define PMAX 3136
#define PIVW 144   // 128 floats + 4-float pad per 32-float group (bank stagger)

typedef unsigned long long ull;

// Scratch: RECIPROCAL of diag(inv(b_covs[p]))[d], stored [D][P].
__device__ float g_rdinv[DIMD * PMAX];

// ---- packed f32x2 helpers (Blackwell sm_103a) ------------------------------
__device__ __forceinline__ ull pack2(float lo, float hi) {
    ull r; asm("mov.b64 %0, {%1, %2};" : "=l"(r) : "f"(lo), "f"(hi)); return r;
}
__device__ __forceinline__ float2 unpack2(ull v) {
    float2 r; asm("mov.b64 {%0, %1}, %2;" : "=f"(r.x), "=f"(r.y) : "l"(v)); return r;
}
__device__ __forceinline__ ull fma2(ull a, ull b, ull c) {
    ull d; asm("fma.rn.f32x2 %0, %1, %2, %3;" : "=l"(d) : "l"(a), "l"(b), "l"(c)); return d;
}
__device__ __forceinline__ ull mul2(ull a, ull b) {
    ull d; asm("mul.rn.f32x2 %0, %1, %2;" : "=l"(d) : "l"(a), "l"(b)); return d;
}
// Fast reciprocal: rcp.approx + 1 Newton step (fp32-accurate).
__device__ __forceinline__ float frcp(float x) {
    float r; asm("rcp.approx.ftz.f32 %0, %1;" : "=f"(r) : "f"(x));
    return r * fmaf(-x, r, 2.0f);
}

// ---------------------------------------------------------------------------
// Phase A: packed-f32x2 Gauss-Jordan (R13 = best 482us), plus ONE change:
// pivbuf is padded 4 floats per 32-float group. R13's profile (L1 71%) and
// bank arithmetic show the pivot-row loads were 2-way bank-conflicted
// (tx*32B addresses -> banks {0,8,16,24} repeat). With the pad, each 8-lane
// LDS.128 phase hits banks {0,8,16,24,4,12,20,28}: conflict-free, halving
// the dominant LDS wavefront cost.
// ---------------------------------------------------------------------------
template<int KQ>
__device__ __forceinline__ void gj_step(
    ull (&Tp)[8][4],
    float (&colbuf)[2][DIMD], float (&pivbuf)[2][PIVW],
    int kk, int ty, int tx, int R0, int C0, int CP)
{
    constexpr int BUF  = KQ & 1;
    constexpr int NBUF = BUF ^ 1;
    const int k = (kk << 3) + KQ;

    float pv  = frcp(colbuf[BUF][k]);
    float npv = -pv;
    ull npv2  = pack2(npv, npv);

    float ci[8];
    {
        const float4* c4 = reinterpret_cast<const float4*>(&colbuf[BUF][R0]);
        float4 v0 = c4[0], v1 = c4[1];
        ci[0]=v0.x; ci[1]=v0.y; ci[2]=v0.z; ci[3]=v0.w;
        ci[4]=v1.x; ci[5]=v1.y; ci[6]=v1.z; ci[7]=v1.w;
    }
    ull ci2[8];
#pragma unroll
    for (int a = 0; a < 8; a++) ci2[a] = pack2(ci[a], ci[a]);

    ull rj2[4];
    {
        const ulonglong2* r4 = reinterpret_cast<const ulonglong2*>(&pivbuf[BUF][CP]);
        ulonglong2 u0 = r4[0], u1 = r4[1];
        rj2[0]=u0.x; rj2[1]=u0.y; rj2[2]=u1.x; rj2[3]=u1.y;
    }
    ull sn2[4];                       // -(row_k * pv)
#pragma unroll
    for (int b = 0; b < 4; b++) sn2[b] = mul2(rj2[b], npv2);

    // Rank-1 update: 32 packed FMAs.
#pragma unroll
    for (int a = 0; a < 8; a++)
#pragma unroll
        for (int b = 0; b < 4; b++)
            Tp[a][b] = fma2(ci2[a], sn2[b], Tp[a][b]);

    // Pivot-row fixup: M[k][j] = row_k[j] * pv.
    if (kk == ty) {
        ull pv2 = pack2(pv, pv);
#pragma unroll
        for (int b = 0; b < 4; b++) Tp[KQ][b] = mul2(rj2[b], pv2);
    }
    // Pivot-col fixup: M[i][k] = -ci[i]*pv; M[k][k] = pv. (After row fixup.)
    if (kk == tx) {
        constexpr int PB = KQ >> 1;
#pragma unroll
        for (int a = 0; a < 8; a++) {
            float2 h = unpack2(Tp[a][PB]);
            float v = (R0 + a == k) ? pv : ci[a] * npv;
            if (KQ & 1) h.y = v; else h.x = v;
            Tp[a][PB] = pack2(h.x, h.y);
        }
    }

    // Stage next pivot column/row from the UPDATED matrix.
    if (k + 1 < DIMD) {
        constexpr int KNQ = (KQ + 1) & 7;
        constexpr int PBN = KNQ >> 1;
        const int kkn = kk + ((KQ + 1) >> 3);
        if (kkn == tx) {
#pragma unroll
            for (int a = 0; a < 8; a++) {
                float2 h = unpack2(Tp[a][PBN]);
                colbuf[NBUF][R0 + a] = (KNQ & 1) ? h.y : h.x;
            }
        }
        if (kkn == ty) {
            ulonglong2* d4 = reinterpret_cast<ulonglong2*>(&pivbuf[NBUF][CP]);
            d4[0] = make_ulonglong2(Tp[KNQ][0], Tp[KNQ][1]);
            d4[1] = make_ulonglong2(Tp[KNQ][2], Tp[KNQ][3]);
        }
    }
    __syncthreads();
}

__global__ __launch_bounds__(256, 2)
void inv_diag_kernel(const float* __restrict__ covs, int P)
{
    int p = blockIdx.x;
    const float* A = covs + (size_t)p * DIMD * DIMD;

    int tid = threadIdx.x;
    int ty = tid >> 4;
    int tx = tid & 15;
    int R0 = ty << 3;
    int C0 = tx << 3;
    int CP = C0 + ((C0 >> 5) << 2);   // bank-staggered pivbuf base

    ull Tp[8][4];     // 8 rows x 4 packed col-pairs = 8x8 fp32 tile
#pragma unroll
    for (int a = 0; a < 8; a++) {
        const ulonglong2* src =
            reinterpret_cast<const ulonglong2*>(A + (size_t)(R0 + a) * DIMD + C0);
        ulonglong2 v0 = src[0], v1 = src[1];
        Tp[a][0]=v0.x; Tp[a][1]=v0.y; Tp[a][2]=v1.x; Tp[a][3]=v1.y;
    }

    __shared__ __align__(16) float colbuf[2][DIMD];   // raw pivot column M[:,k]
    __shared__ __align__(16) float pivbuf[2][PIVW];   // raw pivot row (padded)

    // Stage step 0.
    if (tx == 0) {
#pragma unroll
        for (int a = 0; a < 8; a++) colbuf[0][R0 + a] = unpack2(Tp[a][0]).x;
    }
    if (ty == 0) {
        ulonglong2* d4 = reinterpret_cast<ulonglong2*>(&pivbuf[0][CP]);
        d4[0] = make_ulonglong2(Tp[0][0], Tp[0][1]);
        d4[1] = make_ulonglong2(Tp[0][2], Tp[0][3]);
    }
    __syncthreads();

#pragma unroll 1
    for (int kk = 0; kk < 16; kk++) {
        gj_step<0>(Tp, colbuf, pivbuf, kk, ty, tx, R0, C0, CP);
        gj_step<1>(Tp, colbuf, pivbuf, kk, ty, tx, R0, C0, CP);
        gj_step<2>(Tp, colbuf, pivbuf, kk, ty, tx, R0, C0, CP);
        gj_step<3>(Tp, colbuf, pivbuf, kk, ty, tx, R0, C0, CP);
        gj_step<4>(Tp, colbuf, pivbuf, kk, ty, tx, R0, C0, CP);
        gj_step<5>(Tp, colbuf, pivbuf, kk, ty, tx, R0, C0, CP);
        gj_step<6>(Tp, colbuf, pivbuf, kk, ty, tx, R0, C0, CP);
        gj_step<7>(Tp, colbuf, pivbuf, kk, ty, tx, R0, C0, CP);
    }

    // Registers now hold inv(A). Emit reciprocal of its diagonal.
    if (ty == tx) {
#pragma unroll
        for (int a = 0; a < 8; a++) {
            float2 h = unpack2(Tp[a][a >> 1]);
            float dv = (a & 1) ? h.y : h.x;
            g_rdinv[(size_t)(R0 + a) * P + p] = frcp(dv);
        }
    }
}

// ncu alignment: 3 launches per kernel_launch call => the profiled launch
// (index 3 of the timed sequence) is call 2's inv_diag_kernel.
__global__ void nop_pad_kernel() {}

// ---------------------------------------------------------------------------
// Phase B: streaming whitening + cosine similarity, coalesced:
// block = 256 threads = 64 outputs x 4 d-quarters; a warp's 32 lanes read 32
// consecutive p => full 128B transactions. Cross-quarter reduction via smem.
// ---------------------------------------------------------------------------
__global__ void ace_kernel(const float* __restrict__ X,
                           const float* __restrict__ bmean,
                           const float* __restrict__ covs,
                           const float* __restrict__ sig,
                           const int* __restrict__ covtype,
                           float* __restrict__ out,
                           int B, int P)
{
    int t    = threadIdx.x;
    int sub  = t >> 6;
    int slot = t & 63;
    int idx  = blockIdx.x * 64 + slot;
    bool valid = idx < B * P;
    int b = valid ? idx / P : 0;
    int p = valid ? idx - b * P : 0;
    int ct = *covtype;

    float ww = 0.f, ws = 0.f, ss = 0.f;

    if (valid) {
        if (ct == 0) {
            for (int m = sub * 32; m < sub * 32 + 32; m++) {
                float w = 0.f;
                const float* cr = covs + ((size_t)p * DIMD + m) * DIMD;
                for (int d = 0; d < DIMD; d++) {
                    float xc = X[((size_t)b * DIMD + d) * P + p] - bmean[(size_t)d * P + p];
                    w = fmaf(xc, cr[d], w);
                }
                float s = sig[(size_t)m * P + p];
                ww = fmaf(w, w, ww);
                ws = fmaf(w, s, ws);
                ss = fmaf(s, s, ss);
            }
        } else {
            bool use_diag = (ct == 1);
            int d0 = sub * 32;
#pragma unroll 16
            for (int i = 0; i < 32; i++) {
                int d = d0 + i;
                float xc = X[((size_t)b * DIMD + d) * P + p] - bmean[(size_t)d * P + p];
                float s  = sig[(size_t)d * P + p];
                float w  = use_diag ? (xc * g_rdinv[(size_t)d * P + p]) : xc;
                ww = fmaf(w, w, ww);
                ws = fmaf(w, s, ws);
                ss = fmaf(s, s, ss);
            }
        }
    }

    __shared__ float sred[3][4][64];
    sred[0][sub][slot] = ww;
    sred[1][sub][slot] = ws;
    sred[2][sub][slot] = ss;
    __syncthreads();

    if (sub == 0 && valid) {
        float tw = 0.f, ts = 0.f, tq = 0.f;
#pragma unroll
        for (int q = 0; q < 4; q++) {
            tw += sred[0][q][slot];
            ts += sred[1][q][slot];
            tq += sred[2][q][slot];
        }
        float denom = fmaxf(sqrtf(tw), 1e-12f) * fmaxf(sqrtf(tq), 1e-12f);
        out[idx] = ts / denom;
    }
}

extern "C" void kernel_launch(void* const* d_in, const int* in_sizes, int n_in,
                              void* d_out, int out_size)
{
    const float* X      = (const float*)d_in[0];
    const float* bmean  = (const float*)d_in[1];
    const float* covs   = (const float*)d_in[2];
    const float* sig    = (const float*)d_in[3];
    const int*   ctype  = (const int*)d_in[4];
    float*       out    = (float*)d_out;

    int P = in_sizes[2] / (DIMD * DIMD);           // 3136
    int B = in_sizes[0] / (DIMD * P);              // 32

    inv_diag_kernel<<<P, 256>>>(covs, P);

    int total = B * P;
    ace_kernel<<<(total + 63) / 64, 256>>>(X, bmean, covs, sig, ctype, out, B, P);

    nop_pad_kernel<<<1, 32>>>();   // keep ncu aimed at inv_diag_kernel
}